// round 7
// baseline (speedup 1.0000x reference)
#include <cuda_runtime.h>
#include <math.h>
#include <cstdint>

#define B_CONST 2
#define H_NUM   16
#define HD      32

typedef unsigned long long u64;

// ---------------- device scratch ----------------
__device__ float g_q [2*2048*512];
__device__ float g_k [2*2048*512];
__device__ float g_v [2*2048*512];
__device__ float g_ao[2*2048*512];
__device__ int g_gcols[64];
__device__ int g_gcount;

// ---------------- packed f32x2 helpers ----------------
__device__ __forceinline__ u64 pack2(float lo, float hi) {
    u64 r; asm("mov.b64 %0, {%1, %2};" : "=l"(r) : "f"(lo), "f"(hi)); return r;
}
__device__ __forceinline__ void unpack2(u64 v, float& lo, float& hi) {
    asm("mov.b64 {%0, %1}, %2;" : "=f"(lo), "=f"(hi) : "l"(v));
}
__device__ __forceinline__ u64 fma2(u64 a, u64 b, u64 c) {
    u64 d; asm("fma.rn.f32x2 %0, %1, %2, %3;" : "=l"(d) : "l"(a), "l"(b), "l"(c)); return d;
}
__device__ __forceinline__ u64 mul2(u64 a, u64 b) {
    u64 d; asm("mul.rn.f32x2 %0, %1, %2;" : "=l"(d) : "l"(a), "l"(b)); return d;
}

// ---------------- global-token column list ----------------
__global__ void glist_kernel(int S, const int* __restrict__ Gptr) {
    if (threadIdx.x != 0 || blockIdx.x != 0) return;
    int G = *Gptr;
    int n = 0;
    if (G > 0) {
        int stride = S / (G + 1);
        if (G == 1) {
            g_gcols[n++] = stride;
        } else {
            double stp = (double)(S - 2 * stride) / (double)(G - 1);
            for (int t = 0; t < G && n < 64; t++) {
                long long gi = (t == G - 1)
                    ? (long long)(S - stride)
                    : (long long)((double)t * stp + (double)stride);
                bool dup = false;
                for (int u = 0; u < n; u++) if (g_gcols[u] == (int)gi) dup = true;
                if (!dup) g_gcols[n++] = (int)gi;
            }
        }
    }
    g_gcount = n;
}

// ---------------- TF32 mma.sync GEMM (R5 config): C = (A@W^T + b) * alpha ---
#define BMG 128
#define BNG 128
#define BKG 32
#define SSTR 36
#define GEMM_SMEM (2 * (BMG + BNG) * SSTR * 4)   // 73728 bytes

__device__ __forceinline__ uint32_t f2tf32(float x) {
    uint32_t r;
    asm("cvt.rna.tf32.f32 %0, %1;" : "=r"(r) : "f"(x));
    return r;
}

__device__ __forceinline__ void mma_tf32(float* c, const uint32_t* a, const uint32_t* b) {
    asm volatile(
        "mma.sync.aligned.m16n8k8.row.col.f32.tf32.tf32.f32 "
        "{%0,%1,%2,%3}, {%4,%5,%6,%7}, {%8,%9}, {%0,%1,%2,%3};"
        : "+f"(c[0]), "+f"(c[1]), "+f"(c[2]), "+f"(c[3])
        : "r"(a[0]), "r"(a[1]), "r"(a[2]), "r"(a[3]), "r"(b[0]), "r"(b[1]));
}

__device__ void gemm_core(const float* __restrict__ A, const float* __restrict__ W,
                          const float* __restrict__ bias, float* __restrict__ C,
                          int M, int N, int K, float alpha, float* sm) {
    float* As = sm;
    float* Bs = sm + 2 * BMG * SSTR;

    int tid = threadIdx.x;
    int warp = tid >> 5, lane = tid & 31;
    int warp_m = warp >> 2;
    int warp_n = warp & 3;
    int gr = lane >> 2, gc = lane & 3;

    int bm = blockIdx.y * BMG;
    int bn = blockIdx.x * BNG;

    int lrow = tid >> 3;
    int lc4  = (tid & 7) * 4;

    const float* Ap = A + (size_t)(bm + lrow) * K + lc4;
    const float* Wp = W + (size_t)(bn + lrow) * K + lc4;

    float c[4][4][4];
#pragma unroll
    for (int t = 0; t < 4; t++)
#pragma unroll
        for (int u = 0; u < 4; u++)
#pragma unroll
            for (int e = 0; e < 4; e++) c[t][u][e] = 0.f;

    float4 areg[4], breg[4];
    int nch = K / BKG;

#pragma unroll
    for (int it = 0; it < 4; it++) {
        areg[it] = *(const float4*)(Ap + (size_t)it * 32 * K);
        breg[it] = *(const float4*)(Wp + (size_t)it * 32 * K);
    }
#pragma unroll
    for (int it = 0; it < 4; it++) {
        float* da = As + (lrow + it * 32) * SSTR + lc4;
        float* db = Bs + (lrow + it * 32) * SSTR + lc4;
        ((uint32_t*)da)[0] = f2tf32(areg[it].x); ((uint32_t*)da)[1] = f2tf32(areg[it].y);
        ((uint32_t*)da)[2] = f2tf32(areg[it].z); ((uint32_t*)da)[3] = f2tf32(areg[it].w);
        ((uint32_t*)db)[0] = f2tf32(breg[it].x); ((uint32_t*)db)[1] = f2tf32(breg[it].y);
        ((uint32_t*)db)[2] = f2tf32(breg[it].z); ((uint32_t*)db)[3] = f2tf32(breg[it].w);
    }
    __syncthreads();

    for (int ch = 0; ch < nch; ch++) {
        int buf = ch & 1;
        if (ch + 1 < nch) {
            int k0n = (ch + 1) * BKG;
#pragma unroll
            for (int it = 0; it < 4; it++) {
                areg[it] = *(const float4*)(Ap + (size_t)it * 32 * K + k0n);
                breg[it] = *(const float4*)(Wp + (size_t)it * 32 * K + k0n);
            }
        }
        const uint32_t* as = (const uint32_t*)(As + buf * BMG * SSTR + warp_m * 64 * SSTR);
        const uint32_t* bs = (const uint32_t*)(Bs + buf * BNG * SSTR + warp_n * 32 * SSTR);
#pragma unroll
        for (int ks = 0; ks < 4; ks++) {
            int k0 = ks * 8;
            uint32_t af[4][4], bf[4][2];
#pragma unroll
            for (int t = 0; t < 4; t++) {
                int row = t * 16 + gr;
                af[t][0] = as[row * SSTR + k0 + gc];
                af[t][1] = as[(row + 8) * SSTR + k0 + gc];
                af[t][2] = as[row * SSTR + k0 + gc + 4];
                af[t][3] = as[(row + 8) * SSTR + k0 + gc + 4];
            }
#pragma unroll
            for (int u = 0; u < 4; u++) {
                int col = u * 8 + gr;
                bf[u][0] = bs[col * SSTR + k0 + gc];
                bf[u][1] = bs[col * SSTR + k0 + gc + 4];
            }
#pragma unroll
            for (int t = 0; t < 4; t++)
#pragma unroll
                for (int u = 0; u < 4; u++)
                    mma_tf32(c[t][u], af[t], bf[u]);
        }
        __syncthreads();
        if (ch + 1 < nch) {
            int nbuf = (ch + 1) & 1;
#pragma unroll
            for (int it = 0; it < 4; it++) {
                float* da = As + nbuf * BMG * SSTR + (lrow + it * 32) * SSTR + lc4;
                float* db = Bs + nbuf * BNG * SSTR + (lrow + it * 32) * SSTR + lc4;
                ((uint32_t*)da)[0] = f2tf32(areg[it].x); ((uint32_t*)da)[1] = f2tf32(areg[it].y);
                ((uint32_t*)da)[2] = f2tf32(areg[it].z); ((uint32_t*)da)[3] = f2tf32(areg[it].w);
                ((uint32_t*)db)[0] = f2tf32(breg[it].x); ((uint32_t*)db)[1] = f2tf32(breg[it].y);
                ((uint32_t*)db)[2] = f2tf32(breg[it].z); ((uint32_t*)db)[3] = f2tf32(breg[it].w);
            }
            __syncthreads();
        }
    }

#pragma unroll
    for (int t = 0; t < 4; t++) {
        int row = bm + warp_m * 64 + t * 16 + gr;
#pragma unroll
        for (int u = 0; u < 4; u++) {
            int col = bn + warp_n * 32 + u * 8 + 2 * gc;
            float2 bb = *(const float2*)(bias + col);
            float2 o0, o1;
            o0.x = (c[t][u][0] + bb.x) * alpha;
            o0.y = (c[t][u][1] + bb.y) * alpha;
            o1.x = (c[t][u][2] + bb.x) * alpha;
            o1.y = (c[t][u][3] + bb.y) * alpha;
            *(float2*)(C + (size_t)row * N + col) = o0;
            *(float2*)(C + (size_t)(row + 8) * N + col) = o1;
        }
    }
}

__global__ __launch_bounds__(256)
void qkv_gemm_kernel(const float* q_in, const float* k_in, const float* v_in,
                     const float* Wq, const float* Wk, const float* Wv,
                     const float* bq, const float* bk, const float* bv,
                     float* qo, float* ko, float* vo,
                     int M, int N, int K, float scaling,
                     const float* __restrict__ temp_ptr) {
    extern __shared__ float smg[];
    int z = blockIdx.z;
    const float* A; const float* W; const float* bias; float* C; float alpha;
    if (z == 0)      { A = q_in; W = Wq; bias = bq; C = qo; alpha = scaling * (*temp_ptr); }
    else if (z == 1) { A = k_in; W = Wk; bias = bk; C = ko; alpha = 1.0f; }
    else             { A = v_in; W = Wv; bias = bv; C = vo; alpha = 1.0f; }
    gemm_core(A, W, bias, C, M, N, K, alpha, smg);
}

__global__ __launch_bounds__(256)
void oproj_gemm_kernel(const float* __restrict__ A, const float* __restrict__ W,
                       const float* __restrict__ bias, float* __restrict__ C,
                       int M, int N, int K) {
    extern __shared__ float smg[];
    gemm_core(A, W, bias, C, M, N, K, 1.0f, smg);
}

// ---------------- sparse flash attention v5: 2 adjacent rows / thread -------
// Thread t owns rows ia=i0+2t, ib=ia+1. Ranges are monotone in i, so the
// per-thread union is [rlo_a, rhi_b) and per-row masking needs ONE compare:
// row a: j < rhi_a; row b: j >= rlo_b.
#define AT_BM 256
#define AT_BN 64
#define KS_STR 36
#define ATT_SMEM (2 * AT_BN * KS_STR * 4 + 64)

__global__ void sparse_attn_kernel(int T, int S, int E, const int* __restrict__ Wptr) {
    extern __shared__ float sm[];
    float* Ks = sm;                      // [AT_BN][KS_STR]
    float* Vs = sm + AT_BN * KS_STR;     // [AT_BN][KS_STR]

    int b = blockIdx.z, h = blockIdx.y;
    int i0 = blockIdx.x * AT_BM;
    int t = threadIdx.x;
    int ia = i0 + 2 * t, ib = ia + 1;

    u64 q2a[16], q2b[16];
    {
        const float* qa = g_q + ((size_t)(b * T + ia)) * E + h * HD;
        const float* qb = g_q + ((size_t)(b * T + ib)) * E + h * HD;
#pragma unroll
        for (int d8 = 0; d8 < 8; d8++) {
            ulonglong2 va = *(const ulonglong2*)(qa + d8 * 4);
            ulonglong2 vb = *(const ulonglong2*)(qb + d8 * 4);
            q2a[d8 * 2] = va.x; q2a[d8 * 2 + 1] = va.y;
            q2b[d8 * 2] = vb.x; q2b[d8 * 2 + 1] = vb.y;
        }
    }

    float mra = -INFINITY, la = 0.f;
    float mrb = -INFINITY, lb = 0.f;
    u64 acc2a[16], acc2b[16];
#pragma unroll
    for (int d = 0; d < 16; d++) { acc2a[d] = 0ull; acc2b[d] = 0ull; }

    int Wl = *Wptr;
    int ov = Wl / 4, step = Wl - ov;

    int klo_a = (ia >= Wl) ? (ia - Wl) / step + 1 : 0;
    int khi_a = ia / step;
    int rlo_a = max(0, klo_a * step - ov);
    int rhi_a = min(S, khi_a * step + Wl + ov);
    int klo_b = (ib >= Wl) ? (ib - Wl) / step + 1 : 0;
    int khi_b = ib / step;
    int rlo_b = max(0, klo_b * step - ov);
    int rhi_b = min(S, khi_b * step + Wl + ov);

    int cklo = (i0 >= Wl) ? (i0 - Wl) / step + 1 : 0;
    int ckhi = (i0 + AT_BM - 1) / step;
    int c_lo = max(0, cklo * step - ov);
    int c_hi = min(S, ckhi * step + Wl + ov);

    const float* kbase = g_k + (size_t)b * S * E + h * HD;
    const float* vbase = g_v + (size_t)b * S * E + h * HD;

    int ldrow = t >> 1, ldhalf = (t & 1) * 16;

    for (int j0 = c_lo & ~(AT_BN - 1); j0 < c_hi; j0 += AT_BN) {
        {
            const float* kp = kbase + (size_t)(j0 + ldrow) * E + ldhalf;
            const float* vp = vbase + (size_t)(j0 + ldrow) * E + ldhalf;
#pragma unroll
            for (int c = 0; c < 16; c += 4) {
                *(float4*)&Ks[ldrow * KS_STR + ldhalf + c] = *(const float4*)(kp + c);
                *(float4*)&Vs[ldrow * KS_STR + ldhalf + c] = *(const float4*)(vp + c);
            }
        }
        __syncthreads();

        int jlo = max(rlo_a, j0) - j0;
        int jhi = min(rhi_b, j0 + AT_BN) - j0;

        for (int jc = jlo; jc < jhi; jc += 4) {
            float sa[4], sb[4];
            float ca = -INFINITY, cb = -INFINITY;
#pragma unroll
            for (int c = 0; c < 4; c++) {
                sa[c] = -INFINITY; sb[c] = -INFINITY;
                int jj = jc + c;
                if (jj < jhi) {
                    const ulonglong2* kr = (const ulonglong2*)&Ks[jj * KS_STR];
                    u64 za0 = 0ull, za1 = 0ull, zb0 = 0ull, zb1 = 0ull;
#pragma unroll
                    for (int d8 = 0; d8 < 8; d8++) {
                        ulonglong2 kk = kr[d8];
                        za0 = fma2(q2a[d8 * 2],     kk.x, za0);
                        za1 = fma2(q2a[d8 * 2 + 1], kk.y, za1);
                        zb0 = fma2(q2b[d8 * 2],     kk.x, zb0);
                        zb1 = fma2(q2b[d8 * 2 + 1], kk.y, zb1);
                    }
                    float a0, a1, a2, a3;
                    unpack2(za0, a0, a1); unpack2(za1, a2, a3);
                    float da = (a0 + a2) + (a1 + a3);
                    unpack2(zb0, a0, a1); unpack2(zb1, a2, a3);
                    float db = (a0 + a2) + (a1 + a3);
                    int j = j0 + jj;
                    if (j < rhi_a)  { sa[c] = da; ca = fmaxf(ca, da); }
                    if (j >= rlo_b) { sb[c] = db; cb = fmaxf(cb, db); }
                }
            }
            float mna = fmaxf(mra, ca);
            if (mna > mra) {
                if (mra > -INFINITY) {
                    float cs = __expf(mra - mna);
                    la *= cs;
                    u64 cs2 = pack2(cs, cs);
#pragma unroll
                    for (int d = 0; d < 16; d++) acc2a[d] = mul2(acc2a[d], cs2);
                }
                mra = mna;
            }
            float mnb = fmaxf(mrb, cb);
            if (mnb > mrb) {
                if (mrb > -INFINITY) {
                    float cs = __expf(mrb - mnb);
                    lb *= cs;
                    u64 cs2 = pack2(cs, cs);
#pragma unroll
                    for (int d = 0; d < 16; d++) acc2b[d] = mul2(acc2b[d], cs2);
                }
                mrb = mnb;
            }
            bool aa = mra > -INFINITY, ab = mrb > -INFINITY;
#pragma unroll
            for (int c = 0; c < 4; c++) {
                float pa = aa ? __expf(sa[c] - mra) : 0.f;
                float pb = ab ? __expf(sb[c] - mrb) : 0.f;
                la += pa; lb += pb;
                int jv = min(jc + c, AT_BN - 1);   // clamp: masked lanes read junk*0
                u64 pa2 = pack2(pa, pa);
                u64 pb2 = pack2(pb, pb);
                const ulonglong2* vr = (const ulonglong2*)&Vs[jv * KS_STR];
#pragma unroll
                for (int d8 = 0; d8 < 8; d8++) {
                    ulonglong2 vv = vr[d8];
                    acc2a[d8 * 2]     = fma2(pa2, vv.x, acc2a[d8 * 2]);
                    acc2a[d8 * 2 + 1] = fma2(pa2, vv.y, acc2a[d8 * 2 + 1]);
                    acc2b[d8 * 2]     = fma2(pb2, vv.x, acc2b[d8 * 2]);
                    acc2b[d8 * 2 + 1] = fma2(pb2, vv.y, acc2b[d8 * 2 + 1]);
                }
            }
        }
        __syncthreads();
    }

    // gather pass: global columns outside each row's [rlo, rhi)
    int ng = g_gcount;
    if (ng > 0) {
        for (int idx = t; idx < ng * 2; idx += blockDim.x) {
            int row = idx >> 1, half = (idx & 1) * 16;
            int j = g_gcols[row];
            const float* kp = kbase + (size_t)j * E + half;
            const float* vp = vbase + (size_t)j * E + half;
#pragma unroll
            for (int c = 0; c < 16; c += 4) {
                *(float4*)&Ks[row * KS_STR + half + c] = *(const float4*)(kp + c);
                *(float4*)&Vs[row * KS_STR + half + c] = *(const float4*)(vp + c);
            }
        }
        __syncthreads();

        for (int jc = 0; jc < ng; jc += 4) {
            float sa[4], sb[4];
            float ca = -INFINITY, cb = -INFINITY;
#pragma unroll
            for (int c = 0; c < 4; c++) {
                sa[c] = -INFINITY; sb[c] = -INFINITY;
                if (jc + c < ng) {
                    int j = g_gcols[jc + c];
                    bool na = (j < rlo_a || j >= rhi_a);
                    bool nb = (j < rlo_b || j >= rhi_b);
                    if (na || nb) {
                        const ulonglong2* kr = (const ulonglong2*)&Ks[(jc + c) * KS_STR];
                        u64 za0 = 0ull, za1 = 0ull, zb0 = 0ull, zb1 = 0ull;
#pragma unroll
                        for (int d8 = 0; d8 < 8; d8++) {
                            ulonglong2 kk = kr[d8];
                            za0 = fma2(q2a[d8 * 2],     kk.x, za0);
                            za1 = fma2(q2a[d8 * 2 + 1], kk.y, za1);
                            zb0 = fma2(q2b[d8 * 2],     kk.x, zb0);
                            zb1 = fma2(q2b[d8 * 2 + 1], kk.y, zb1);
                        }
                        float a0, a1, a2, a3;
                        unpack2(za0, a0, a1); unpack2(za1, a2, a3);
                        float da = (a0 + a2) + (a1 + a3);
                        unpack2(zb0, a0, a1); unpack2(zb1, a2, a3);
                        float db = (a0 + a2) + (a1 + a3);
                        if (na) { sa[c] = da; ca = fmaxf(ca, da); }
                        if (nb) { sb[c] = db; cb = fmaxf(cb, db); }
                    }
                }
            }
            float mna = fmaxf(mra, ca);
            if (mna > mra) {
                if (mra > -INFINITY) {
                    float cs = __expf(mra - mna);
                    la *= cs;
                    u64 cs2 = pack2(cs, cs);
#pragma unroll
                    for (int d = 0; d < 16; d++) acc2a[d] = mul2(acc2a[d], cs2);
                }
                mra = mna;
            }
            float mnb = fmaxf(mrb, cb);
            if (mnb > mrb) {
                if (mrb > -INFINITY) {
                    float cs = __expf(mrb - mnb);
                    lb *= cs;
                    u64 cs2 = pack2(cs, cs);
#pragma unroll
                    for (int d = 0; d < 16; d++) acc2b[d] = mul2(acc2b[d], cs2);
                }
                mrb = mnb;
            }
            bool aa = mra > -INFINITY, ab = mrb > -INFINITY;
#pragma unroll
            for (int c = 0; c < 4; c++) {
                float pa = aa ? __expf(sa[c] - mra) : 0.f;
                float pb = ab ? __expf(sb[c] - mrb) : 0.f;
                la += pa; lb += pb;
                int jv = min(jc + c, AT_BN - 1);
                u64 pa2 = pack2(pa, pa);
                u64 pb2 = pack2(pb, pb);
                const ulonglong2* vr = (const ulonglong2*)&Vs[jv * KS_STR];
#pragma unroll
                for (int d8 = 0; d8 < 8; d8++) {
                    ulonglong2 vv = vr[d8];
                    acc2a[d8 * 2]     = fma2(pa2, vv.x, acc2a[d8 * 2]);
                    acc2a[d8 * 2 + 1] = fma2(pa2, vv.y, acc2a[d8 * 2 + 1]);
                    acc2b[d8 * 2]     = fma2(pb2, vv.x, acc2b[d8 * 2]);
                    acc2b[d8 * 2 + 1] = fma2(pb2, vv.y, acc2b[d8 * 2 + 1]);
                }
            }
        }
    }

    float inva = 1.0f / la;
    float invb = 1.0f / lb;
    float* oa = g_ao + ((size_t)(b * T + ia)) * E + h * HD;
    float* ob = g_ao + ((size_t)(b * T + ib)) * E + h * HD;
#pragma unroll
    for (int d8 = 0; d8 < 8; d8++) {
        float x0, x1, x2, x3;
        unpack2(acc2a[d8 * 2],     x0, x1);
        unpack2(acc2a[d8 * 2 + 1], x2, x3);
        float4 o;
        o.x = x0 * inva; o.y = x1 * inva; o.z = x2 * inva; o.w = x3 * inva;
        *(float4*)(oa + d8 * 4) = o;
        unpack2(acc2b[d8 * 2],     x0, x1);
        unpack2(acc2b[d8 * 2 + 1], x2, x3);
        o.x = x0 * invb; o.y = x1 * invb; o.z = x2 * invb; o.w = x3 * invb;
        *(float4*)(ob + d8 * 4) = o;
    }
}

// ---------------- launch -----------------------------------------------------
extern "C" void kernel_launch(void* const* d_in, const int* in_sizes, int n_in,
                              void* d_out, int out_size) {
    const float* query = (const float*)d_in[0];
    const float* key_  = (const float*)d_in[1];
    const float* value = (const float*)d_in[2];
    const float* Wq = (const float*)d_in[3];
    const float* bq = (const float*)d_in[4];
    const float* Wk = (const float*)d_in[5];
    const float* bk = (const float*)d_in[6];
    const float* Wv = (const float*)d_in[7];
    const float* bv = (const float*)d_in[8];
    const float* Wo = (const float*)d_in[9];
    const float* bo = (const float*)d_in[10];
    const float* temperature = (const float*)d_in[11];
    const int* wsize = (const int*)d_in[12];
    const int* gnum  = (const int*)d_in[13];
    float* out = (float*)d_out;

    int E = in_sizes[4];                 // 512
    int B = B_CONST;
    int T = in_sizes[0] / (B * E);       // 2048
    int S = in_sizes[1] / (B * E);       // 2048
    int M = B * T;                       // 4096
    int hd = E / H_NUM;

    float *qb, *kb, *vb, *aob;
    cudaGetSymbolAddress((void**)&qb,  g_q);
    cudaGetSymbolAddress((void**)&kb,  g_k);
    cudaGetSymbolAddress((void**)&vb,  g_v);
    cudaGetSymbolAddress((void**)&aob, g_ao);

    glist_kernel<<<1, 32>>>(S, gnum);

    cudaFuncSetAttribute(qkv_gemm_kernel,
                         cudaFuncAttributeMaxDynamicSharedMemorySize, GEMM_SMEM);
    cudaFuncSetAttribute(oproj_gemm_kernel,
                         cudaFuncAttributeMaxDynamicSharedMemorySize, GEMM_SMEM);

    float scaling = 1.0f / sqrtf((float)hd);
    dim3 qkv_grid(E / BNG, M / BMG, 3);          // (4, 32, 3)
    qkv_gemm_kernel<<<qkv_grid, 256, GEMM_SMEM>>>(
        query, key_, value, Wq, Wk, Wv, bq, bk, bv,
        qb, kb, vb, M, E, E, scaling, temperature);

    cudaFuncSetAttribute(sparse_attn_kernel,
                         cudaFuncAttributeMaxDynamicSharedMemorySize, ATT_SMEM);
    sparse_attn_kernel<<<dim3(T / AT_BM, H_NUM, B), AT_BM / 2, ATT_SMEM>>>(T, S, E, wsize);

    dim3 ogrid(E / BNG, M / BMG);                // (4, 32)
    oproj_gemm_kernel<<<ogrid, 256, GEMM_SMEM>>>(aob, Wo, bo, out, M, E, E);
}

// round 8
// speedup vs baseline: 1.1798x; 1.1798x over previous
#include <cuda_runtime.h>
#include <math.h>
#include <cstdint>

#define B_CONST 2
#define H_NUM   16
#define HD      32

typedef unsigned long long u64;

// ---------------- device scratch ----------------
__device__ float g_q [2*2048*512];
__device__ float g_k [2*2048*512];
__device__ float g_v [2*2048*512];
__device__ float g_ao[2*2048*512];
__device__ int g_gcols[64];
__device__ int g_gcount;

// ---------------- packed f32x2 helpers ----------------
__device__ __forceinline__ u64 pack2(float lo, float hi) {
    u64 r; asm("mov.b64 %0, {%1, %2};" : "=l"(r) : "f"(lo), "f"(hi)); return r;
}
__device__ __forceinline__ void unpack2(u64 v, float& lo, float& hi) {
    asm("mov.b64 {%0, %1}, %2;" : "=f"(lo), "=f"(hi) : "l"(v));
}
__device__ __forceinline__ u64 fma2(u64 a, u64 b, u64 c) {
    u64 d; asm("fma.rn.f32x2 %0, %1, %2, %3;" : "=l"(d) : "l"(a), "l"(b), "l"(c)); return d;
}
__device__ __forceinline__ u64 mul2(u64 a, u64 b) {
    u64 d; asm("mul.rn.f32x2 %0, %1, %2;" : "=l"(d) : "l"(a), "l"(b)); return d;
}

// ---------------- global-token column list ----------------
__global__ void glist_kernel(int S, const int* __restrict__ Gptr) {
    if (threadIdx.x != 0 || blockIdx.x != 0) return;
    int G = *Gptr;
    int n = 0;
    if (G > 0) {
        int stride = S / (G + 1);
        if (G == 1) {
            g_gcols[n++] = stride;
        } else {
            double stp = (double)(S - 2 * stride) / (double)(G - 1);
            for (int t = 0; t < G && n < 64; t++) {
                long long gi = (t == G - 1)
                    ? (long long)(S - stride)
                    : (long long)((double)t * stp + (double)stride);
                bool dup = false;
                for (int u = 0; u < n; u++) if (g_gcols[u] == (int)gi) dup = true;
                if (!dup) g_gcols[n++] = (int)gi;
            }
        }
    }
    g_gcount = n;
}

// ---------------- TF32 mma.sync GEMM (R5 config): C = (A@W^T + b) * alpha ---
#define BMG 128
#define BNG 128
#define BKG 32
#define SSTR 36
#define GEMM_SMEM (2 * (BMG + BNG) * SSTR * 4)   // 73728 bytes

__device__ __forceinline__ uint32_t f2tf32(float x) {
    uint32_t r;
    asm("cvt.rna.tf32.f32 %0, %1;" : "=r"(r) : "f"(x));
    return r;
}

__device__ __forceinline__ void mma_tf32(float* c, const uint32_t* a, const uint32_t* b) {
    asm volatile(
        "mma.sync.aligned.m16n8k8.row.col.f32.tf32.tf32.f32 "
        "{%0,%1,%2,%3}, {%4,%5,%6,%7}, {%8,%9}, {%0,%1,%2,%3};"
        : "+f"(c[0]), "+f"(c[1]), "+f"(c[2]), "+f"(c[3])
        : "r"(a[0]), "r"(a[1]), "r"(a[2]), "r"(a[3]), "r"(b[0]), "r"(b[1]));
}

__device__ void gemm_core(const float* __restrict__ A, const float* __restrict__ W,
                          const float* __restrict__ bias, float* __restrict__ C,
                          int M, int N, int K, float alpha, float* sm) {
    float* As = sm;
    float* Bs = sm + 2 * BMG * SSTR;

    int tid = threadIdx.x;
    int warp = tid >> 5, lane = tid & 31;
    int warp_m = warp >> 2;
    int warp_n = warp & 3;
    int gr = lane >> 2, gc = lane & 3;

    int bm = blockIdx.y * BMG;
    int bn = blockIdx.x * BNG;

    int lrow = tid >> 3;
    int lc4  = (tid & 7) * 4;

    const float* Ap = A + (size_t)(bm + lrow) * K + lc4;
    const float* Wp = W + (size_t)(bn + lrow) * K + lc4;

    float c[4][4][4];
#pragma unroll
    for (int t = 0; t < 4; t++)
#pragma unroll
        for (int u = 0; u < 4; u++)
#pragma unroll
            for (int e = 0; e < 4; e++) c[t][u][e] = 0.f;

    float4 areg[4], breg[4];
    int nch = K / BKG;

#pragma unroll
    for (int it = 0; it < 4; it++) {
        areg[it] = *(const float4*)(Ap + (size_t)it * 32 * K);
        breg[it] = *(const float4*)(Wp + (size_t)it * 32 * K);
    }
#pragma unroll
    for (int it = 0; it < 4; it++) {
        float* da = As + (lrow + it * 32) * SSTR + lc4;
        float* db = Bs + (lrow + it * 32) * SSTR + lc4;
        ((uint32_t*)da)[0] = f2tf32(areg[it].x); ((uint32_t*)da)[1] = f2tf32(areg[it].y);
        ((uint32_t*)da)[2] = f2tf32(areg[it].z); ((uint32_t*)da)[3] = f2tf32(areg[it].w);
        ((uint32_t*)db)[0] = f2tf32(breg[it].x); ((uint32_t*)db)[1] = f2tf32(breg[it].y);
        ((uint32_t*)db)[2] = f2tf32(breg[it].z); ((uint32_t*)db)[3] = f2tf32(breg[it].w);
    }
    __syncthreads();

    for (int ch = 0; ch < nch; ch++) {
        int buf = ch & 1;
        if (ch + 1 < nch) {
            int k0n = (ch + 1) * BKG;
#pragma unroll
            for (int it = 0; it < 4; it++) {
                areg[it] = *(const float4*)(Ap + (size_t)it * 32 * K + k0n);
                breg[it] = *(const float4*)(Wp + (size_t)it * 32 * K + k0n);
            }
        }
        const uint32_t* as = (const uint32_t*)(As + buf * BMG * SSTR + warp_m * 64 * SSTR);
        const uint32_t* bs = (const uint32_t*)(Bs + buf * BNG * SSTR + warp_n * 32 * SSTR);
#pragma unroll
        for (int ks = 0; ks < 4; ks++) {
            int k0 = ks * 8;
            uint32_t af[4][4], bf[4][2];
#pragma unroll
            for (int t = 0; t < 4; t++) {
                int row = t * 16 + gr;
                af[t][0] = as[row * SSTR + k0 + gc];
                af[t][1] = as[(row + 8) * SSTR + k0 + gc];
                af[t][2] = as[row * SSTR + k0 + gc + 4];
                af[t][3] = as[(row + 8) * SSTR + k0 + gc + 4];
            }
#pragma unroll
            for (int u = 0; u < 4; u++) {
                int col = u * 8 + gr;
                bf[u][0] = bs[col * SSTR + k0 + gc];
                bf[u][1] = bs[col * SSTR + k0 + gc + 4];
            }
#pragma unroll
            for (int t = 0; t < 4; t++)
#pragma unroll
                for (int u = 0; u < 4; u++)
                    mma_tf32(c[t][u], af[t], bf[u]);
        }
        __syncthreads();
        if (ch + 1 < nch) {
            int nbuf = (ch + 1) & 1;
#pragma unroll
            for (int it = 0; it < 4; it++) {
                float* da = As + nbuf * BMG * SSTR + (lrow + it * 32) * SSTR + lc4;
                float* db = Bs + nbuf * BNG * SSTR + (lrow + it * 32) * SSTR + lc4;
                ((uint32_t*)da)[0] = f2tf32(areg[it].x); ((uint32_t*)da)[1] = f2tf32(areg[it].y);
                ((uint32_t*)da)[2] = f2tf32(areg[it].z); ((uint32_t*)da)[3] = f2tf32(areg[it].w);
                ((uint32_t*)db)[0] = f2tf32(breg[it].x); ((uint32_t*)db)[1] = f2tf32(breg[it].y);
                ((uint32_t*)db)[2] = f2tf32(breg[it].z); ((uint32_t*)db)[3] = f2tf32(breg[it].w);
            }
            __syncthreads();
        }
    }

#pragma unroll
    for (int t = 0; t < 4; t++) {
        int row = bm + warp_m * 64 + t * 16 + gr;
#pragma unroll
        for (int u = 0; u < 4; u++) {
            int col = bn + warp_n * 32 + u * 8 + 2 * gc;
            float2 bb = *(const float2*)(bias + col);
            float2 o0, o1;
            o0.x = (c[t][u][0] + bb.x) * alpha;
            o0.y = (c[t][u][1] + bb.y) * alpha;
            o1.x = (c[t][u][2] + bb.x) * alpha;
            o1.y = (c[t][u][3] + bb.y) * alpha;
            *(float2*)(C + (size_t)row * N + col) = o0;
            *(float2*)(C + (size_t)(row + 8) * N + col) = o1;
        }
    }
}

__global__ __launch_bounds__(256)
void qkv_gemm_kernel(const float* q_in, const float* k_in, const float* v_in,
                     const float* Wq, const float* Wk, const float* Wv,
                     const float* bq, const float* bk, const float* bv,
                     float* qo, float* ko, float* vo,
                     int M, int N, int K, float scaling,
                     const float* __restrict__ temp_ptr) {
    extern __shared__ float smg[];
    int z = blockIdx.z;
    const float* A; const float* W; const float* bias; float* C; float alpha;
    if (z == 0)      { A = q_in; W = Wq; bias = bq; C = qo; alpha = scaling * (*temp_ptr); }
    else if (z == 1) { A = k_in; W = Wk; bias = bk; C = ko; alpha = 1.0f; }
    else             { A = v_in; W = Wv; bias = bv; C = vo; alpha = 1.0f; }
    gemm_core(A, W, bias, C, M, N, K, alpha, smg);
}

__global__ __launch_bounds__(256)
void oproj_gemm_kernel(const float* __restrict__ A, const float* __restrict__ W,
                       const float* __restrict__ bias, float* __restrict__ C,
                       int M, int N, int K) {
    extern __shared__ float smg[];
    gemm_core(A, W, bias, C, M, N, K, 1.0f, smg);
}

// ---------------- sparse flash attention v6: warp-uniform broadcast --------
// Thread t owns row i0+t. The column loop is WARP-UNIFORM (union of the
// warp's 32 row ranges, which are monotone => contiguous union), so all 32
// lanes read the SAME K/V smem address each step -> LDS broadcast, 32x less
// crossbar traffic. Per-row exactness via one compare (j>=rlo && j<rhi).
#define AT_BM 128
#define AT_BN 64
#define KS_STR 36
#define ATT_SMEM (2 * AT_BN * KS_STR * 4 + 64)

__global__ __launch_bounds__(128)
void sparse_attn_kernel(int T, int S, int E, const int* __restrict__ Wptr) {
    extern __shared__ float sm[];
    float* Ks = sm;                      // [AT_BN][KS_STR]
    float* Vs = sm + AT_BN * KS_STR;     // [AT_BN][KS_STR]

    int b = blockIdx.z, h = blockIdx.y;
    int i0 = blockIdx.x * AT_BM;
    int t = threadIdx.x;
    int i = i0 + t;

    const float* qrow = g_q + ((size_t)(b * T + i)) * E + h * HD;
    u64 q2[16];
#pragma unroll
    for (int d8 = 0; d8 < 8; d8++) {
        ulonglong2 v = *(const ulonglong2*)(qrow + d8 * 4);
        q2[d8 * 2] = v.x; q2[d8 * 2 + 1] = v.y;
    }

    float mrow = -INFINITY, l = 0.f;
    u64 acc2[16];
#pragma unroll
    for (int d = 0; d < 16; d++) acc2[d] = 0ull;

    int Wl = *Wptr;
    int ov = Wl / 4, step = Wl - ov;

    // this row's exact contiguous range
    int klo = (i >= Wl) ? (i - Wl) / step + 1 : 0;
    int khi = i / step;
    int rlo = max(0, klo * step - ov);
    int rhi = min(S, khi * step + Wl + ov);

    // warp union range (rows wbase .. wbase+31; monotone => contiguous union)
    int wbase = i0 + (t & ~31);
    int wlast = wbase + 31;
    int wklo = (wbase >= Wl) ? (wbase - Wl) / step + 1 : 0;
    int wkhi = wlast / step;
    int w_lo = max(0, wklo * step - ov);
    int w_hi = min(S, wkhi * step + Wl + ov);

    // CTA union range (tile loop bounds)
    int cklo = (i0 >= Wl) ? (i0 - Wl) / step + 1 : 0;
    int ckhi = (i0 + AT_BM - 1) / step;
    int c_lo = max(0, cklo * step - ov);
    int c_hi = min(S, ckhi * step + Wl + ov);

    const float* kbase = g_k + (size_t)b * S * E + h * HD;
    const float* vbase = g_v + (size_t)b * S * E + h * HD;

    int ldrow = t >> 1, ldhalf = (t & 1) * 16;

    for (int j0 = c_lo & ~(AT_BN - 1); j0 < c_hi; j0 += AT_BN) {
        {
            const float* kp = kbase + (size_t)(j0 + ldrow) * E + ldhalf;
            const float* vp = vbase + (size_t)(j0 + ldrow) * E + ldhalf;
#pragma unroll
            for (int c = 0; c < 16; c += 4) {
                *(float4*)&Ks[ldrow * KS_STR + ldhalf + c] = *(const float4*)(kp + c);
                *(float4*)&Vs[ldrow * KS_STR + ldhalf + c] = *(const float4*)(vp + c);
            }
        }
        __syncthreads();

        // WARP-UNIFORM bounds: identical for all 32 lanes
        int jlo = max(w_lo, j0) - j0;
        int jhi = min(w_hi, j0 + AT_BN) - j0;

        for (int jc = jlo; jc < jhi; jc += 8) {
            float s[8];
            float cmax = -INFINITY;
#pragma unroll
            for (int c = 0; c < 8; c++) {
                s[c] = -INFINITY;
                int jj = jc + c;
                if (jj < jhi) {
                    // broadcast: same address across the warp
                    const ulonglong2* kr = (const ulonglong2*)&Ks[jj * KS_STR];
                    u64 z0 = 0ull, z1 = 0ull;
#pragma unroll
                    for (int d8 = 0; d8 < 8; d8++) {
                        ulonglong2 kk = kr[d8];
                        z0 = fma2(q2[d8 * 2],     kk.x, z0);
                        z1 = fma2(q2[d8 * 2 + 1], kk.y, z1);
                    }
                    float a0, a1, b0, b1;
                    unpack2(z0, a0, a1);
                    unpack2(z1, b0, b1);
                    int j = j0 + jj;
                    if (j >= rlo && j < rhi) {           // per-row exact mask
                        s[c] = (a0 + b0) + (a1 + b1);
                        cmax = fmaxf(cmax, s[c]);
                    }
                }
            }
            if (cmax > -INFINITY) {
                float mnew = fmaxf(mrow, cmax);
                if (mnew > mrow) {
                    if (mrow > -INFINITY) {
                        float cs = __expf(mrow - mnew);
                        l *= cs;
                        u64 cs2 = pack2(cs, cs);
#pragma unroll
                        for (int d = 0; d < 16; d++) acc2[d] = mul2(acc2[d], cs2);
                    }
                    mrow = mnew;
                }
#pragma unroll
                for (int c = 0; c < 8; c++) {
                    float p = __expf(s[c] - mrow);       // masked -> 0
                    l += p;
                    int jv = min(jc + c, AT_BN - 1);     // clamp; p=0 there
                    u64 pp = pack2(p, p);
                    const ulonglong2* vr = (const ulonglong2*)&Vs[jv * KS_STR];
#pragma unroll
                    for (int d8 = 0; d8 < 8; d8++) {
                        ulonglong2 vv = vr[d8];
                        acc2[d8 * 2]     = fma2(pp, vv.x, acc2[d8 * 2]);
                        acc2[d8 * 2 + 1] = fma2(pp, vv.y, acc2[d8 * 2 + 1]);
                    }
                }
            }
        }
        __syncthreads();
    }

    // gather pass: global columns outside this row's [rlo, rhi) (broadcast)
    int ng = g_gcount;
    if (ng > 0) {
        for (int idx = t; idx < ng * 2; idx += AT_BM) {
            int row = idx >> 1, half = (idx & 1) * 16;
            int j = g_gcols[row];
            const float* kp = kbase + (size_t)j * E + half;
            const float* vp = vbase + (size_t)j * E + half;
#pragma unroll
            for (int c = 0; c < 16; c += 4) {
                *(float4*)&Ks[row * KS_STR + half + c] = *(const float4*)(kp + c);
                *(float4*)&Vs[row * KS_STR + half + c] = *(const float4*)(vp + c);
            }
        }
        __syncthreads();

        for (int jc = 0; jc < ng; jc += 8) {
            float s[8];
            float cmax = -INFINITY;
#pragma unroll
            for (int c = 0; c < 8; c++) {
                s[c] = -INFINITY;
                if (jc + c < ng) {
                    int j = g_gcols[jc + c];
                    if (j < rlo || j >= rhi) {
                        const ulonglong2* kr = (const ulonglong2*)&Ks[(jc + c) * KS_STR];
                        u64 z0 = 0ull, z1 = 0ull;
#pragma unroll
                        for (int d8 = 0; d8 < 8; d8++) {
                            ulonglong2 kk = kr[d8];
                            z0 = fma2(q2[d8 * 2],     kk.x, z0);
                            z1 = fma2(q2[d8 * 2 + 1], kk.y, z1);
                        }
                        float a0, a1, b0, b1;
                        unpack2(z0, a0, a1);
                        unpack2(z1, b0, b1);
                        s[c] = (a0 + b0) + (a1 + b1);
                        cmax = fmaxf(cmax, s[c]);
                    }
                }
            }
            if (cmax > -INFINITY) {
                float mnew = fmaxf(mrow, cmax);
                if (mnew > mrow) {
                    if (mrow > -INFINITY) {
                        float cs = __expf(mrow - mnew);
                        l *= cs;
                        u64 cs2 = pack2(cs, cs);
#pragma unroll
                        for (int d = 0; d < 16; d++) acc2[d] = mul2(acc2[d], cs2);
                    }
                    mrow = mnew;
                }
#pragma unroll
                for (int c = 0; c < 8; c++) {
                    float p = __expf(s[c] - mrow);
                    l += p;
                    int jv = min(jc + c, AT_BN - 1);
                    u64 pp = pack2(p, p);
                    const ulonglong2* vr = (const ulonglong2*)&Vs[jv * KS_STR];
#pragma unroll
                    for (int d8 = 0; d8 < 8; d8++) {
                        ulonglong2 vv = vr[d8];
                        acc2[d8 * 2]     = fma2(pp, vv.x, acc2[d8 * 2]);
                        acc2[d8 * 2 + 1] = fma2(pp, vv.y, acc2[d8 * 2 + 1]);
                    }
                }
            }
        }
    }

    float inv = 1.0f / l;
    float* orow = g_ao + ((size_t)(b * T + i)) * E + h * HD;
#pragma unroll
    for (int d8 = 0; d8 < 8; d8++) {
        float x0, x1, x2, x3;
        unpack2(acc2[d8 * 2],     x0, x1);
        unpack2(acc2[d8 * 2 + 1], x2, x3);
        float4 o;
        o.x = x0 * inv; o.y = x1 * inv; o.z = x2 * inv; o.w = x3 * inv;
        *(float4*)(orow + d8 * 4) = o;
    }
}

// ---------------- launch -----------------------------------------------------
extern "C" void kernel_launch(void* const* d_in, const int* in_sizes, int n_in,
                              void* d_out, int out_size) {
    const float* query = (const float*)d_in[0];
    const float* key_  = (const float*)d_in[1];
    const float* value = (const float*)d_in[2];
    const float* Wq = (const float*)d_in[3];
    const float* bq = (const float*)d_in[4];
    const float* Wk = (const float*)d_in[5];
    const float* bk = (const float*)d_in[6];
    const float* Wv = (const float*)d_in[7];
    const float* bv = (const float*)d_in[8];
    const float* Wo = (const float*)d_in[9];
    const float* bo = (const float*)d_in[10];
    const float* temperature = (const float*)d_in[11];
    const int* wsize = (const int*)d_in[12];
    const int* gnum  = (const int*)d_in[13];
    float* out = (float*)d_out;

    int E = in_sizes[4];                 // 512
    int B = B_CONST;
    int T = in_sizes[0] / (B * E);       // 2048
    int S = in_sizes[1] / (B * E);       // 2048
    int M = B * T;                       // 4096
    int hd = E / H_NUM;

    float *qb, *kb, *vb, *aob;
    cudaGetSymbolAddress((void**)&qb,  g_q);
    cudaGetSymbolAddress((void**)&kb,  g_k);
    cudaGetSymbolAddress((void**)&vb,  g_v);
    cudaGetSymbolAddress((void**)&aob, g_ao);

    glist_kernel<<<1, 32>>>(S, gnum);

    cudaFuncSetAttribute(qkv_gemm_kernel,
                         cudaFuncAttributeMaxDynamicSharedMemorySize, GEMM_SMEM);
    cudaFuncSetAttribute(oproj_gemm_kernel,
                         cudaFuncAttributeMaxDynamicSharedMemorySize, GEMM_SMEM);

    float scaling = 1.0f / sqrtf((float)hd);
    dim3 qkv_grid(E / BNG, M / BMG, 3);          // (4, 32, 3)
    qkv_gemm_kernel<<<qkv_grid, 256, GEMM_SMEM>>>(
        query, key_, value, Wq, Wk, Wv, bq, bk, bv,
        qb, kb, vb, M, E, E, scaling, temperature);

    cudaFuncSetAttribute(sparse_attn_kernel,
                         cudaFuncAttributeMaxDynamicSharedMemorySize, ATT_SMEM);
    sparse_attn_kernel<<<dim3(T / AT_BM, H_NUM, B), AT_BM, ATT_SMEM>>>(T, S, E, wsize);

    dim3 ogrid(E / BNG, M / BMG);                // (4, 32)
    oproj_gemm_kernel<<<ogrid, 256, GEMM_SMEM>>>(aob, Wo, bo, out, M, E, E);
}

// round 9
// speedup vs baseline: 1.2760x; 1.0815x over previous
#include <cuda_runtime.h>
#include <math.h>
#include <cstdint>

#define B_CONST 2
#define H_NUM   16
#define HD      32

typedef unsigned long long u64;

// ---------------- device scratch ----------------
__device__ float g_q [2*2048*512];
__device__ float g_k [2*2048*512];
__device__ float g_v [2*2048*512];
__device__ float g_ao[2*2048*512];
__device__ int g_gcols[64];
__device__ int g_gcount;

// ---------------- packed f32x2 helpers ----------------
__device__ __forceinline__ u64 pack2(float lo, float hi) {
    u64 r; asm("mov.b64 %0, {%1, %2};" : "=l"(r) : "f"(lo), "f"(hi)); return r;
}
__device__ __forceinline__ void unpack2(u64 v, float& lo, float& hi) {
    asm("mov.b64 {%0, %1}, %2;" : "=f"(lo), "=f"(hi) : "l"(v));
}
__device__ __forceinline__ u64 fma2(u64 a, u64 b, u64 c) {
    u64 d; asm("fma.rn.f32x2 %0, %1, %2, %3;" : "=l"(d) : "l"(a), "l"(b), "l"(c)); return d;
}
__device__ __forceinline__ u64 mul2(u64 a, u64 b) {
    u64 d; asm("mul.rn.f32x2 %0, %1, %2;" : "=l"(d) : "l"(a), "l"(b)); return d;
}
__device__ __forceinline__ u64 add2(u64 a, u64 b) {
    u64 d; asm("add.rn.f32x2 %0, %1, %2;" : "=l"(d) : "l"(a), "l"(b)); return d;
}

// ---------------- global-token column list ----------------
__global__ void glist_kernel(int S, const int* __restrict__ Gptr) {
    if (threadIdx.x != 0 || blockIdx.x != 0) return;
    int G = *Gptr;
    int n = 0;
    if (G > 0) {
        int stride = S / (G + 1);
        if (G == 1) {
            g_gcols[n++] = stride;
        } else {
            double stp = (double)(S - 2 * stride) / (double)(G - 1);
            for (int t = 0; t < G && n < 64; t++) {
                long long gi = (t == G - 1)
                    ? (long long)(S - stride)
                    : (long long)((double)t * stp + (double)stride);
                bool dup = false;
                for (int u = 0; u < n; u++) if (g_gcols[u] == (int)gi) dup = true;
                if (!dup) g_gcols[n++] = (int)gi;
            }
        }
    }
    g_gcount = n;
}

// ---------------- TF32 mma.sync GEMM: C = (A@W^T + b) * alpha ---------------
#define BMG 128
#define BNG 128
#define BKG 32
#define SSTR 36
#define GEMM_SMEM (2 * (BMG + BNG) * SSTR * 4)   // 73728 bytes

__device__ __forceinline__ uint32_t f2tf32(float x) {
    uint32_t r;
    asm("cvt.rna.tf32.f32 %0, %1;" : "=r"(r) : "f"(x));
    return r;
}

__device__ __forceinline__ void mma_tf32(float* c, const uint32_t* a, const uint32_t* b) {
    asm volatile(
        "mma.sync.aligned.m16n8k8.row.col.f32.tf32.tf32.f32 "
        "{%0,%1,%2,%3}, {%4,%5,%6,%7}, {%8,%9}, {%0,%1,%2,%3};"
        : "+f"(c[0]), "+f"(c[1]), "+f"(c[2]), "+f"(c[3])
        : "r"(a[0]), "r"(a[1]), "r"(a[2]), "r"(a[3]), "r"(b[0]), "r"(b[1]));
}

__device__ void gemm_core(const float* __restrict__ A, const float* __restrict__ W,
                          const float* __restrict__ bias, float* __restrict__ C,
                          int M, int N, int K, float alpha, float* sm) {
    float* As = sm;
    float* Bs = sm + 2 * BMG * SSTR;

    int tid = threadIdx.x;
    int warp = tid >> 5, lane = tid & 31;
    int warp_m = warp >> 2;
    int warp_n = warp & 3;
    int gr = lane >> 2, gc = lane & 3;

    int bm = blockIdx.y * BMG;
    int bn = blockIdx.x * BNG;

    int lrow = tid >> 3;
    int lc4  = (tid & 7) * 4;

    const float* Ap = A + (size_t)(bm + lrow) * K + lc4;
    const float* Wp = W + (size_t)(bn + lrow) * K + lc4;

    float c[4][4][4];
#pragma unroll
    for (int t = 0; t < 4; t++)
#pragma unroll
        for (int u = 0; u < 4; u++)
#pragma unroll
            for (int e = 0; e < 4; e++) c[t][u][e] = 0.f;

    float4 areg[4], breg[4];
    int nch = K / BKG;

#pragma unroll
    for (int it = 0; it < 4; it++) {
        areg[it] = *(const float4*)(Ap + (size_t)it * 32 * K);
        breg[it] = *(const float4*)(Wp + (size_t)it * 32 * K);
    }
#pragma unroll
    for (int it = 0; it < 4; it++) {
        float* da = As + (lrow + it * 32) * SSTR + lc4;
        float* db = Bs + (lrow + it * 32) * SSTR + lc4;
        ((uint32_t*)da)[0] = f2tf32(areg[it].x); ((uint32_t*)da)[1] = f2tf32(areg[it].y);
        ((uint32_t*)da)[2] = f2tf32(areg[it].z); ((uint32_t*)da)[3] = f2tf32(areg[it].w);
        ((uint32_t*)db)[0] = f2tf32(breg[it].x); ((uint32_t*)db)[1] = f2tf32(breg[it].y);
        ((uint32_t*)db)[2] = f2tf32(breg[it].z); ((uint32_t*)db)[3] = f2tf32(breg[it].w);
    }
    __syncthreads();

    for (int ch = 0; ch < nch; ch++) {
        int buf = ch & 1;
        if (ch + 1 < nch) {
            int k0n = (ch + 1) * BKG;
#pragma unroll
            for (int it = 0; it < 4; it++) {
                areg[it] = *(const float4*)(Ap + (size_t)it * 32 * K + k0n);
                breg[it] = *(const float4*)(Wp + (size_t)it * 32 * K + k0n);
            }
        }
        const uint32_t* as = (const uint32_t*)(As + buf * BMG * SSTR + warp_m * 64 * SSTR);
        const uint32_t* bs = (const uint32_t*)(Bs + buf * BNG * SSTR + warp_n * 32 * SSTR);
#pragma unroll
        for (int ks = 0; ks < 4; ks++) {
            int k0 = ks * 8;
            uint32_t af[4][4], bf[4][2];
#pragma unroll
            for (int t = 0; t < 4; t++) {
                int row = t * 16 + gr;
                af[t][0] = as[row * SSTR + k0 + gc];
                af[t][1] = as[(row + 8) * SSTR + k0 + gc];
                af[t][2] = as[row * SSTR + k0 + gc + 4];
                af[t][3] = as[(row + 8) * SSTR + k0 + gc + 4];
            }
#pragma unroll
            for (int u = 0; u < 4; u++) {
                int col = u * 8 + gr;
                bf[u][0] = bs[col * SSTR + k0 + gc];
                bf[u][1] = bs[col * SSTR + k0 + gc + 4];
            }
#pragma unroll
            for (int t = 0; t < 4; t++)
#pragma unroll
                for (int u = 0; u < 4; u++)
                    mma_tf32(c[t][u], af[t], bf[u]);
        }
        __syncthreads();
        if (ch + 1 < nch) {
            int nbuf = (ch + 1) & 1;
#pragma unroll
            for (int it = 0; it < 4; it++) {
                float* da = As + nbuf * BMG * SSTR + (lrow + it * 32) * SSTR + lc4;
                float* db = Bs + nbuf * BNG * SSTR + (lrow + it * 32) * SSTR + lc4;
                ((uint32_t*)da)[0] = f2tf32(areg[it].x); ((uint32_t*)da)[1] = f2tf32(areg[it].y);
                ((uint32_t*)da)[2] = f2tf32(areg[it].z); ((uint32_t*)da)[3] = f2tf32(areg[it].w);
                ((uint32_t*)db)[0] = f2tf32(breg[it].x); ((uint32_t*)db)[1] = f2tf32(breg[it].y);
                ((uint32_t*)db)[2] = f2tf32(breg[it].z); ((uint32_t*)db)[3] = f2tf32(breg[it].w);
            }
            __syncthreads();
        }
    }

#pragma unroll
    for (int t = 0; t < 4; t++) {
        int row = bm + warp_m * 64 + t * 16 + gr;
#pragma unroll
        for (int u = 0; u < 4; u++) {
            int col = bn + warp_n * 32 + u * 8 + 2 * gc;
            float2 bb = *(const float2*)(bias + col);
            float2 o0, o1;
            o0.x = (c[t][u][0] + bb.x) * alpha;
            o0.y = (c[t][u][1] + bb.y) * alpha;
            o1.x = (c[t][u][2] + bb.x) * alpha;
            o1.y = (c[t][u][3] + bb.y) * alpha;
            *(float2*)(C + (size_t)row * N + col) = o0;
            *(float2*)(C + (size_t)(row + 8) * N + col) = o1;
        }
    }
}

__global__ __launch_bounds__(256, 2)
void qkv_gemm_kernel(const float* q_in, const float* k_in, const float* v_in,
                     const float* Wq, const float* Wk, const float* Wv,
                     const float* bq, const float* bk, const float* bv,
                     float* qo, float* ko, float* vo,
                     int M, int N, int K, float scaling,
                     const float* __restrict__ temp_ptr) {
    extern __shared__ float smg[];
    int z = blockIdx.z;
    const float* A; const float* W; const float* bias; float* C; float alpha;
    if (z == 0)      { A = q_in; W = Wq; bias = bq; C = qo; alpha = scaling * (*temp_ptr); }
    else if (z == 1) { A = k_in; W = Wk; bias = bk; C = ko; alpha = 1.0f; }
    else             { A = v_in; W = Wv; bias = bv; C = vo; alpha = 1.0f; }
    gemm_core(A, W, bias, C, M, N, K, alpha, smg);
}

__global__ __launch_bounds__(256, 2)
void oproj_gemm_kernel(const float* __restrict__ A, const float* __restrict__ W,
                       const float* __restrict__ bias, float* __restrict__ C,
                       int M, int N, int K) {
    extern __shared__ float smg[];
    gemm_core(A, W, bias, C, M, N, K, 1.0f, smg);
}

// ---------------- sparse flash attention v7 --------------------------------
// v4 structure (per-thread exact bounds) + 4 independent QK chains + add2
// combine + rescale only when the running max changes.
#define AT_BM 128
#define AT_BN 64
#define KS_STR 36
#define ATT_SMEM (2 * AT_BN * KS_STR * 4 + 64)

__global__ __launch_bounds__(128)
void sparse_attn_kernel(int T, int S, int E, const int* __restrict__ Wptr) {
    extern __shared__ float sm[];
    float* Ks = sm;                      // [AT_BN][KS_STR]
    float* Vs = sm + AT_BN * KS_STR;     // [AT_BN][KS_STR]

    int b = blockIdx.z, h = blockIdx.y;
    int i0 = blockIdx.x * AT_BM;
    int t = threadIdx.x;
    int i = i0 + t;

    const float* qrow = g_q + ((size_t)(b * T + i)) * E + h * HD;
    u64 q2[16];
#pragma unroll
    for (int d8 = 0; d8 < 8; d8++) {
        ulonglong2 v = *(const ulonglong2*)(qrow + d8 * 4);
        q2[d8 * 2] = v.x; q2[d8 * 2 + 1] = v.y;
    }

    float mrow = -INFINITY, l = 0.f;
    u64 acc2[16];
#pragma unroll
    for (int d = 0; d < 16; d++) acc2[d] = 0ull;

    int Wl = *Wptr;
    int ov = Wl / 4, step = Wl - ov;

    int klo = (i >= Wl) ? (i - Wl) / step + 1 : 0;
    int khi = i / step;
    int rlo = max(0, klo * step - ov);
    int rhi = min(S, khi * step + Wl + ov);

    int cklo = (i0 >= Wl) ? (i0 - Wl) / step + 1 : 0;
    int ckhi = (i0 + AT_BM - 1) / step;
    int c_lo = max(0, cklo * step - ov);
    int c_hi = min(S, ckhi * step + Wl + ov);

    const float* kbase = g_k + (size_t)b * S * E + h * HD;
    const float* vbase = g_v + (size_t)b * S * E + h * HD;

    int ldrow = t >> 1, ldhalf = (t & 1) * 16;

    for (int j0 = c_lo & ~(AT_BN - 1); j0 < c_hi; j0 += AT_BN) {
        {
            const float* kp = kbase + (size_t)(j0 + ldrow) * E + ldhalf;
            const float* vp = vbase + (size_t)(j0 + ldrow) * E + ldhalf;
#pragma unroll
            for (int c = 0; c < 16; c += 4) {
                *(float4*)&Ks[ldrow * KS_STR + ldhalf + c] = *(const float4*)(kp + c);
                *(float4*)&Vs[ldrow * KS_STR + ldhalf + c] = *(const float4*)(vp + c);
            }
        }
        __syncthreads();

        int jlo = max(rlo, j0) - j0;
        int jhi = min(rhi, j0 + AT_BN) - j0;

        for (int jc = jlo; jc < jhi; jc += 8) {
            float s[8];
            float cmax = -INFINITY;
#pragma unroll
            for (int c = 0; c < 8; c++) {
                s[c] = -INFINITY;
                if (jc + c < jhi) {
                    const ulonglong2* kr = (const ulonglong2*)&Ks[(jc + c) * KS_STR];
                    // 4 independent fma2 chains (depth 4)
                    u64 z0 = 0ull, z1 = 0ull, z2 = 0ull, z3 = 0ull;
#pragma unroll
                    for (int d4 = 0; d4 < 4; d4++) {
                        ulonglong2 k0 = kr[d4 * 2];
                        ulonglong2 k1 = kr[d4 * 2 + 1];
                        z0 = fma2(q2[d4 * 4 + 0], k0.x, z0);
                        z1 = fma2(q2[d4 * 4 + 1], k0.y, z1);
                        z2 = fma2(q2[d4 * 4 + 2], k1.x, z2);
                        z3 = fma2(q2[d4 * 4 + 3], k1.y, z3);
                    }
                    u64 zz = add2(add2(z0, z2), add2(z1, z3));
                    float a0, a1;
                    unpack2(zz, a0, a1);
                    s[c] = a0 + a1;
                    cmax = fmaxf(cmax, s[c]);
                }
            }
            float mnew = fmaxf(mrow, cmax);
            if (mnew > mrow) {
                if (mrow > -INFINITY) {
                    float cs = __expf(mrow - mnew);
                    l *= cs;
                    u64 cs2 = pack2(cs, cs);
#pragma unroll
                    for (int d = 0; d < 16; d++) acc2[d] = mul2(acc2[d], cs2);
                }
                mrow = mnew;
            }
#pragma unroll
            for (int c = 0; c < 8; c++) {
                float p = __expf(s[c] - mrow);       // -inf lanes -> 0
                l += p;
                int jv = min(jc + c, AT_BN - 1);     // clamp; p=0 there
                u64 pp = pack2(p, p);
                const ulonglong2* vr = (const ulonglong2*)&Vs[jv * KS_STR];
#pragma unroll
                for (int d8 = 0; d8 < 8; d8++) {
                    ulonglong2 vv = vr[d8];
                    acc2[d8 * 2]     = fma2(pp, vv.x, acc2[d8 * 2]);
                    acc2[d8 * 2 + 1] = fma2(pp, vv.y, acc2[d8 * 2 + 1]);
                }
            }
        }
        __syncthreads();
    }

    // gather pass: global columns outside this row's [rlo, rhi)
    int ng = g_gcount;
    if (ng > 0) {
        for (int idx = t; idx < ng * 2; idx += AT_BM) {
            int row = idx >> 1, half = (idx & 1) * 16;
            int j = g_gcols[row];
            const float* kp = kbase + (size_t)j * E + half;
            const float* vp = vbase + (size_t)j * E + half;
#pragma unroll
            for (int c = 0; c < 16; c += 4) {
                *(float4*)&Ks[row * KS_STR + half + c] = *(const float4*)(kp + c);
                *(float4*)&Vs[row * KS_STR + half + c] = *(const float4*)(vp + c);
            }
        }
        __syncthreads();

        for (int jc = 0; jc < ng; jc += 8) {
            float s[8];
            float cmax = -INFINITY;
#pragma unroll
            for (int c = 0; c < 8; c++) {
                s[c] = -INFINITY;
                if (jc + c < ng) {
                    int j = g_gcols[jc + c];
                    if (j < rlo || j >= rhi) {
                        const ulonglong2* kr = (const ulonglong2*)&Ks[(jc + c) * KS_STR];
                        u64 z0 = 0ull, z1 = 0ull, z2 = 0ull, z3 = 0ull;
#pragma unroll
                        for (int d4 = 0; d4 < 4; d4++) {
                            ulonglong2 k0 = kr[d4 * 2];
                            ulonglong2 k1 = kr[d4 * 2 + 1];
                            z0 = fma2(q2[d4 * 4 + 0], k0.x, z0);
                            z1 = fma2(q2[d4 * 4 + 1], k0.y, z1);
                            z2 = fma2(q2[d4 * 4 + 2], k1.x, z2);
                            z3 = fma2(q2[d4 * 4 + 3], k1.y, z3);
                        }
                        u64 zz = add2(add2(z0, z2), add2(z1, z3));
                        float a0, a1;
                        unpack2(zz, a0, a1);
                        s[c] = a0 + a1;
                        cmax = fmaxf(cmax, s[c]);
                    }
                }
            }
            if (cmax > -INFINITY) {
                float mnew = fmaxf(mrow, cmax);
                if (mnew > mrow) {
                    if (mrow > -INFINITY) {
                        float cs = __expf(mrow - mnew);
                        l *= cs;
                        u64 cs2 = pack2(cs, cs);
#pragma unroll
                        for (int d = 0; d < 16; d++) acc2[d] = mul2(acc2[d], cs2);
                    }
                    mrow = mnew;
                }
#pragma unroll
                for (int c = 0; c < 8; c++) {
                    float p = __expf(s[c] - mrow);
                    l += p;
                    int jv = min(jc + c, AT_BN - 1);
                    u64 pp = pack2(p, p);
                    const ulonglong2* vr = (const ulonglong2*)&Vs[jv * KS_STR];
#pragma unroll
                    for (int d8 = 0; d8 < 8; d8++) {
                        ulonglong2 vv = vr[d8];
                        acc2[d8 * 2]     = fma2(pp, vv.x, acc2[d8 * 2]);
                        acc2[d8 * 2 + 1] = fma2(pp, vv.y, acc2[d8 * 2 + 1]);
                    }
                }
            }
        }
    }

    float inv = 1.0f / l;
    float* orow = g_ao + ((size_t)(b * T + i)) * E + h * HD;
#pragma unroll
    for (int d8 = 0; d8 < 8; d8++) {
        float x0, x1, x2, x3;
        unpack2(acc2[d8 * 2],     x0, x1);
        unpack2(acc2[d8 * 2 + 1], x2, x3);
        float4 o;
        o.x = x0 * inv; o.y = x1 * inv; o.z = x2 * inv; o.w = x3 * inv;
        *(float4*)(orow + d8 * 4) = o;
    }
}

// ---------------- launch -----------------------------------------------------
extern "C" void kernel_launch(void* const* d_in, const int* in_sizes, int n_in,
                              void* d_out, int out_size) {
    const float* query = (const float*)d_in[0];
    const float* key_  = (const float*)d_in[1];
    const float* value = (const float*)d_in[2];
    const float* Wq = (const float*)d_in[3];
    const float* bq = (const float*)d_in[4];
    const float* Wk = (const float*)d_in[5];
    const float* bk = (const float*)d_in[6];
    const float* Wv = (const float*)d_in[7];
    const float* bv = (const float*)d_in[8];
    const float* Wo = (const float*)d_in[9];
    const float* bo = (const float*)d_in[10];
    const float* temperature = (const float*)d_in[11];
    const int* wsize = (const int*)d_in[12];
    const int* gnum  = (const int*)d_in[13];
    float* out = (float*)d_out;

    int E = in_sizes[4];                 // 512
    int B = B_CONST;
    int T = in_sizes[0] / (B * E);       // 2048
    int S = in_sizes[1] / (B * E);       // 2048
    int M = B * T;                       // 4096
    int hd = E / H_NUM;

    float *qb, *kb, *vb, *aob;
    cudaGetSymbolAddress((void**)&qb,  g_q);
    cudaGetSymbolAddress((void**)&kb,  g_k);
    cudaGetSymbolAddress((void**)&vb,  g_v);
    cudaGetSymbolAddress((void**)&aob, g_ao);

    glist_kernel<<<1, 32>>>(S, gnum);

    cudaFuncSetAttribute(qkv_gemm_kernel,
                         cudaFuncAttributeMaxDynamicSharedMemorySize, GEMM_SMEM);
    cudaFuncSetAttribute(oproj_gemm_kernel,
                         cudaFuncAttributeMaxDynamicSharedMemorySize, GEMM_SMEM);

    float scaling = 1.0f / sqrtf((float)hd);
    dim3 qkv_grid(E / BNG, M / BMG, 3);          // (4, 32, 3)
    qkv_gemm_kernel<<<qkv_grid, 256, GEMM_SMEM>>>(
        query, key_, value, Wq, Wk, Wv, bq, bk, bv,
        qb, kb, vb, M, E, E, scaling, temperature);

    cudaFuncSetAttribute(sparse_attn_kernel,
                         cudaFuncAttributeMaxDynamicSharedMemorySize, ATT_SMEM);
    sparse_attn_kernel<<<dim3(T / AT_BM, H_NUM, B), AT_BM, ATT_SMEM>>>(T, S, E, wsize);

    dim3 ogrid(E / BNG, M / BMG);                // (4, 32)
    oproj_gemm_kernel<<<ogrid, 256, GEMM_SMEM>>>(aob, Wo, bo, out, M, E, E);
}